// round 1
// baseline (speedup 1.0000x reference)
#include <cuda_runtime.h>
#include <math.h>

// Problem constants
#define Bsz 4096
#define Dd  1024
#define Hh  1024
#define FourH 4096
#define Ksrc 1024          // K per source (D == H == 1024)

// GEMM tiling
#define BM 128
#define BN 128
#define BK 16
#define TM 8
#define TN 8
#define NTHREADS 256

// Scratch for pre-activations a = x@Wx + prev_h@Wh + b  (4096 x 4096 fp32, 64 MB)
__device__ float g_a[(size_t)Bsz * FourH];

// ---------------------------------------------------------------------------
// GEMM: g_a[M=4096, N=4096] = x[4096,1024]@Wx[1024,4096]
//                           + prev_h[4096,1024]@Wh[1024,4096] + bias[4096]
// 128x128 block tile, 8x8 per thread, BK=16, gmem->reg prefetch.
// All dims are exact multiples of the tile sizes: no bounds checks.
// ---------------------------------------------------------------------------
__global__ __launch_bounds__(NTHREADS, 2)
void gemm_bias_kernel(const float* __restrict__ x,
                      const float* __restrict__ ph,
                      const float* __restrict__ Wx,
                      const float* __restrict__ Wh,
                      const float* __restrict__ bias)
{
    __shared__ float As[BK][BM];   // transposed A tile
    __shared__ float Bs[BK][BN];

    const int tid = threadIdx.x;
    const int tx  = tid & 15;      // 0..15 -> col group
    const int ty  = tid >> 4;      // 0..15 -> row group

    // A-tile loading map: 128 rows x 16 cols, 2 float4 per thread
    const int aRow = tid >> 2;          // 0..63 (and +64)
    const int aCol = (tid & 3) * 4;     // 0,4,8,12
    // B-tile loading map: 16 rows x 128 cols, 2 float4 per thread
    const int bRow = tid >> 5;          // 0..7 (and +8)
    const int bCol = (tid & 31) * 4;    // 0..124

    const int blockRow = blockIdx.y * BM;
    const int blockCol = blockIdx.x * BN;

    float acc[TM][TN];
    #pragma unroll
    for (int i = 0; i < TM; ++i)
        #pragma unroll
        for (int j = 0; j < TN; ++j) acc[i][j] = 0.0f;

    #pragma unroll 1
    for (int src = 0; src < 2; ++src) {
        const float* Ab = (src == 0 ? x  : ph) + (size_t)blockRow * Ksrc;
        const float* Bb = (src == 0 ? Wx : Wh) + blockCol;

        // ---- prologue: load k-tile 0 ----
        float4 a0 = *(const float4*)(Ab + (size_t)aRow        * Ksrc + aCol);
        float4 a1 = *(const float4*)(Ab + (size_t)(aRow + 64) * Ksrc + aCol);
        float4 b0 = *(const float4*)(Bb + (size_t)bRow       * FourH + bCol);
        float4 b1 = *(const float4*)(Bb + (size_t)(bRow + 8) * FourH + bCol);

        __syncthreads();   // make sure previous compute (src==1 case) is done
        As[aCol + 0][aRow] = a0.x; As[aCol + 1][aRow] = a0.y;
        As[aCol + 2][aRow] = a0.z; As[aCol + 3][aRow] = a0.w;
        As[aCol + 0][aRow + 64] = a1.x; As[aCol + 1][aRow + 64] = a1.y;
        As[aCol + 2][aRow + 64] = a1.z; As[aCol + 3][aRow + 64] = a1.w;
        *(float4*)&Bs[bRow][bCol]     = b0;
        *(float4*)&Bs[bRow + 8][bCol] = b1;
        __syncthreads();

        const int NKT = Ksrc / BK;   // 64
        #pragma unroll 1
        for (int kt = 0; kt < NKT; ++kt) {
            // prefetch next k-tile into registers (overlaps with compute)
            if (kt < NKT - 1) {
                const float* Ak = Ab + (kt + 1) * BK;
                const float* Bk = Bb + (size_t)(kt + 1) * BK * FourH;
                a0 = *(const float4*)(Ak + (size_t)aRow        * Ksrc + aCol);
                a1 = *(const float4*)(Ak + (size_t)(aRow + 64) * Ksrc + aCol);
                b0 = *(const float4*)(Bk + (size_t)bRow       * FourH + bCol);
                b1 = *(const float4*)(Bk + (size_t)(bRow + 8) * FourH + bCol);
            }

            // compute on current smem tile
            #pragma unroll
            for (int kk = 0; kk < BK; ++kk) {
                float af[TM], bf[TN];
                *(float4*)&af[0] = *(const float4*)&As[kk][ty * TM];
                *(float4*)&af[4] = *(const float4*)&As[kk][ty * TM + 4];
                *(float4*)&bf[0] = *(const float4*)&Bs[kk][tx * TN];
                *(float4*)&bf[4] = *(const float4*)&Bs[kk][tx * TN + 4];
                #pragma unroll
                for (int i = 0; i < TM; ++i)
                    #pragma unroll
                    for (int j = 0; j < TN; ++j)
                        acc[i][j] = fmaf(af[i], bf[j], acc[i][j]);
            }
            __syncthreads();

            if (kt < NKT - 1) {
                As[aCol + 0][aRow] = a0.x; As[aCol + 1][aRow] = a0.y;
                As[aCol + 2][aRow] = a0.z; As[aCol + 3][aRow] = a0.w;
                As[aCol + 0][aRow + 64] = a1.x; As[aCol + 1][aRow + 64] = a1.y;
                As[aCol + 2][aRow + 64] = a1.z; As[aCol + 3][aRow + 64] = a1.w;
                *(float4*)&Bs[bRow][bCol]     = b0;
                *(float4*)&Bs[bRow + 8][bCol] = b1;
                __syncthreads();
            }
        }
    }

    // ---- epilogue: add bias, store to scratch ----
    const int gr = blockRow + ty * TM;
    const int gc = blockCol + tx * TN;
    const float4 bb0 = *(const float4*)(bias + gc);
    const float4 bb1 = *(const float4*)(bias + gc + 4);

    #pragma unroll
    for (int i = 0; i < TM; ++i) {
        float4 v0, v1;
        v0.x = acc[i][0] + bb0.x; v0.y = acc[i][1] + bb0.y;
        v0.z = acc[i][2] + bb0.z; v0.w = acc[i][3] + bb0.w;
        v1.x = acc[i][4] + bb1.x; v1.y = acc[i][5] + bb1.y;
        v1.z = acc[i][6] + bb1.z; v1.w = acc[i][7] + bb1.w;
        *(float4*)(&g_a[(size_t)(gr + i) * FourH + gc])     = v0;
        *(float4*)(&g_a[(size_t)(gr + i) * FourH + gc + 4]) = v1;
    }
}

// ---------------------------------------------------------------------------
// LayerNorm over 4H + LSTM gates + cell/hidden update.
// One block per batch row; 256 threads; each thread owns float4 in each of
// the 4 gate segments (256*4 = 1024 = H).
// ---------------------------------------------------------------------------
__device__ __forceinline__ float sigmoidf_(float v) {
    return 1.0f / (1.0f + expf(-v));
}

__global__ __launch_bounds__(256)
void ln_gates_kernel(const float* __restrict__ prev_c,
                     const float* __restrict__ gamma,
                     const float* __restrict__ beta,
                     float* __restrict__ next_h,
                     float* __restrict__ next_c)
{
    const int row = blockIdx.x;
    const int tid = threadIdx.x;
    const int j   = tid * 4;                 // column within each H-segment
    const float* ar = g_a + (size_t)row * FourH;

    // load 16 values (4 per segment)
    float4 v[4];
    #pragma unroll
    for (int s = 0; s < 4; ++s)
        v[s] = *(const float4*)(ar + s * Hh + j);

    float sum = 0.0f, sq = 0.0f;
    #pragma unroll
    for (int s = 0; s < 4; ++s) {
        sum += v[s].x + v[s].y + v[s].z + v[s].w;
        sq  += v[s].x * v[s].x + v[s].y * v[s].y
             + v[s].z * v[s].z + v[s].w * v[s].w;
    }

    // block reduction: warp shuffle + smem across 8 warps
    #pragma unroll
    for (int off = 16; off > 0; off >>= 1) {
        sum += __shfl_xor_sync(0xffffffffu, sum, off);
        sq  += __shfl_xor_sync(0xffffffffu, sq,  off);
    }
    __shared__ float red_sum[8], red_sq[8];
    const int warp = tid >> 5;
    if ((tid & 31) == 0) { red_sum[warp] = sum; red_sq[warp] = sq; }
    __syncthreads();
    float tsum = 0.0f, tsq = 0.0f;
    #pragma unroll
    for (int w = 0; w < 8; ++w) { tsum += red_sum[w]; tsq += red_sq[w]; }

    const float inv_n = 1.0f / (float)FourH;
    const float mu   = tsum * inv_n;
    const float var  = tsq * inv_n - mu * mu;
    const float rstd = rsqrtf(var + 1e-5f);

    // normalize + affine per segment
    float n[4][4];
    #pragma unroll
    for (int s = 0; s < 4; ++s) {
        const float4 gm = *(const float4*)(gamma + s * Hh + j);
        const float4 bt = *(const float4*)(beta  + s * Hh + j);
        n[s][0] = (v[s].x - mu) * rstd * gm.x + bt.x;
        n[s][1] = (v[s].y - mu) * rstd * gm.y + bt.y;
        n[s][2] = (v[s].z - mu) * rstd * gm.z + bt.z;
        n[s][3] = (v[s].w - mu) * rstd * gm.w + bt.w;
    }

    const float4 pc = *(const float4*)(prev_c + (size_t)row * Hh + j);
    const float pcv[4] = {pc.x, pc.y, pc.z, pc.w};

    float4 hc, cc;
    float* hp = &hc.x;
    float* cp = &cc.x;
    #pragma unroll
    for (int c = 0; c < 4; ++c) {
        const float ig = sigmoidf_(n[0][c]);
        const float fg = sigmoidf_(n[1][c]);
        const float og = sigmoidf_(n[2][c]);
        const float gg = tanhf(n[3][c]);
        const float cn = fg * pcv[c] + ig * gg;
        cp[c] = cn;
        hp[c] = og * tanhf(cn);
    }

    *(float4*)(next_h + (size_t)row * Hh + j) = hc;
    *(float4*)(next_c + (size_t)row * Hh + j) = cc;
}

// ---------------------------------------------------------------------------
// Launch
// inputs (metadata order): x, prev_h, prev_c, Wx, Wh, b, ln_gamma, ln_beta
// output: concat(next_h, next_c) -> out_size = 2 * B * H floats
// ---------------------------------------------------------------------------
extern "C" void kernel_launch(void* const* d_in, const int* in_sizes, int n_in,
                              void* d_out, int out_size)
{
    const float* x     = (const float*)d_in[0];
    const float* ph    = (const float*)d_in[1];
    const float* pc    = (const float*)d_in[2];
    const float* Wx    = (const float*)d_in[3];
    const float* Wh    = (const float*)d_in[4];
    const float* bias  = (const float*)d_in[5];
    const float* gamma = (const float*)d_in[6];
    const float* beta  = (const float*)d_in[7];

    float* out    = (float*)d_out;
    float* next_h = out;
    float* next_c = out + (size_t)out_size / 2;

    dim3 grid(FourH / BN, Bsz / BM);   // 32 x 32
    gemm_bias_kernel<<<grid, NTHREADS>>>(x, ph, Wx, Wh, bias);

    ln_gates_kernel<<<Bsz, 256>>>(pc, gamma, beta, next_h, next_c);
}

// round 3
// speedup vs baseline: 3.5923x; 3.5923x over previous
#include <cuda_runtime.h>
#include <cuda_fp16.h>
#include <math.h>
#include <cstdint>

// ---------------------------------------------------------------------------
// Problem constants
// ---------------------------------------------------------------------------
#define Bsz   4096
#define Hh    1024
#define FourH 4096
#define Ktot  2048          // D + H concatenated

// GEMM tiling
#define BM 128
#define BN 128
#define BK 32
#define NKITERS (Ktot / BK)        // 64
#define GTHREADS 256

// SMEM strides (bytes) — padded for conflict-free ldmatrix
#define A_STRIDE 80                 // 64B data + 16B pad
#define B_STRIDE 272                // 256B data + 16B pad
#define A_TILE_BYTES (BM * A_STRIDE)        // 10240
#define B_TILE_BYTES (BK * B_STRIDE)        // 8704
#define OFF_AH 0
#define OFF_AL A_TILE_BYTES
#define OFF_B  (2 * A_TILE_BYTES)
#define STAGE_BYTES (2 * A_TILE_BYTES + B_TILE_BYTES)   // 29184
#define SMEM_TOTAL (2 * STAGE_BYTES)                     // 58368

// ---------------------------------------------------------------------------
// Device scratch
// ---------------------------------------------------------------------------
__device__ float  g_a[(size_t)Bsz * FourH];      // fp32 pre-activations (64 MB)
__device__ __half g_Ah[(size_t)Bsz * Ktot];      // A hi  [4096][2048]
__device__ __half g_Al[(size_t)Bsz * Ktot];      // A lo
__device__ __half g_B [(size_t)Ktot * FourH];    // W fp16 [2048][4096] (k rows, n contig)

// ---------------------------------------------------------------------------
// PTX helpers
// ---------------------------------------------------------------------------
__device__ __forceinline__ uint32_t smem_u32(const void* p) {
    uint32_t a;
    asm("{ .reg .u64 t; cvta.to.shared.u64 t, %1; cvt.u32.u64 %0, t; }" : "=r"(a) : "l"(p));
    return a;
}
__device__ __forceinline__ void cp16(uint32_t smem_addr, const void* gptr) {
    asm volatile("cp.async.cg.shared.global [%0], [%1], 16;" :: "r"(smem_addr), "l"(gptr));
}
#define CP_COMMIT() asm volatile("cp.async.commit_group;" ::: "memory")
#define CP_WAIT(n)  asm volatile("cp.async.wait_group %0;" :: "n"(n) : "memory")

#define LDSM_X4(r0,r1,r2,r3, addr) \
    asm volatile("ldmatrix.sync.aligned.m8n8.x4.shared.b16 {%0,%1,%2,%3}, [%4];" \
                 : "=r"(r0), "=r"(r1), "=r"(r2), "=r"(r3) : "r"(addr))
#define LDSM_X4_T(r0,r1,r2,r3, addr) \
    asm volatile("ldmatrix.sync.aligned.m8n8.x4.trans.shared.b16 {%0,%1,%2,%3}, [%4];" \
                 : "=r"(r0), "=r"(r1), "=r"(r2), "=r"(r3) : "r"(addr))

__device__ __forceinline__ void mma16816(float* c, const uint32_t* a, const uint32_t* b) {
    asm volatile(
        "mma.sync.aligned.m16n8k16.row.col.f32.f16.f16.f32 "
        "{%0,%1,%2,%3}, {%4,%5,%6,%7}, {%8,%9}, {%0,%1,%2,%3};"
        : "+f"(c[0]), "+f"(c[1]), "+f"(c[2]), "+f"(c[3])
        : "r"(a[0]), "r"(a[1]), "r"(a[2]), "r"(a[3]), "r"(b[0]), "r"(b[1]));
}

// ---------------------------------------------------------------------------
// convertA: [x | prev_h] -> fp16 hi/lo, row-major [4096][2048]
// ---------------------------------------------------------------------------
__global__ __launch_bounds__(256)
void convertA_kernel(const float* __restrict__ x, const float* __restrict__ ph) {
    const int idx = blockIdx.x * 256 + threadIdx.x;     // 4096*2048/4 = 2M groups
    const int row = idx >> 9;
    const int col = (idx & 511) * 4;
    const float* src = (col < 1024) ? (x + (size_t)row * 1024 + col)
                                    : (ph + (size_t)row * 1024 + (col - 1024));
    const float4 v = *(const float4*)src;
    const float f[4] = {v.x, v.y, v.z, v.w};
    __half hi[4], lo[4];
    #pragma unroll
    for (int i = 0; i < 4; ++i) {
        hi[i] = __float2half_rn(f[i]);
        lo[i] = __float2half_rn(f[i] - __half2float(hi[i]));
    }
    const size_t off = (size_t)row * Ktot + col;
    *(__half2*)(g_Ah + off)     = __halves2half2(hi[0], hi[1]);
    *(__half2*)(g_Ah + off + 2) = __halves2half2(hi[2], hi[3]);
    *(__half2*)(g_Al + off)     = __halves2half2(lo[0], lo[1]);
    *(__half2*)(g_Al + off + 2) = __halves2half2(lo[2], lo[3]);
}

// ---------------------------------------------------------------------------
// convertB: W = [Wx ; Wh] (natural [k][n] layout) -> fp16
// ---------------------------------------------------------------------------
__global__ __launch_bounds__(256)
void convertB_kernel(const float* __restrict__ Wx, const float* __restrict__ Wh) {
    const int idx = blockIdx.x * 256 + threadIdx.x;     // 2048*4096/4 groups
    const int row = idx >> 10;                          // 4096/4 = 1024 groups/row
    const int col = (idx & 1023) * 4;
    const float* src = (row < 1024) ? (Wx + (size_t)row * FourH + col)
                                    : (Wh + (size_t)(row - 1024) * FourH + col);
    const float4 v = *(const float4*)src;
    const size_t off = (size_t)row * FourH + col;
    *(__half2*)(g_B + off)     = __halves2half2(__float2half_rn(v.x), __float2half_rn(v.y));
    *(__half2*)(g_B + off + 2) = __halves2half2(__float2half_rn(v.z), __float2half_rn(v.w));
}

// ---------------------------------------------------------------------------
// Tensor-core GEMM: g_a = A @ B + bias  (A split fp16 hi/lo, B fp16)
// CTA 128x128, BK=32, 8 warps (4 m x 2 n), warp tile 32x64, double-buffered.
// ---------------------------------------------------------------------------
__global__ __launch_bounds__(GTHREADS, 2)
void gemm_mma_kernel(const float* __restrict__ bias) {
    extern __shared__ char smem[];
    const uint32_t sbase = smem_u32(smem);
    const int tid  = threadIdx.x;
    const int warp = tid >> 5;
    const int lid  = tid & 31;

    const int mBase = blockIdx.y * BM;
    const int nBase = blockIdx.x * BN;

    const int warpM = warp & 3;          // 0..3 -> m offset
    const int warpN = warp >> 2;         // 0..1 -> n offset
    const int wm = warpM * 32;
    const int wn = warpN * 64;

    // per-thread ldmatrix row mapping
    const int aRowInTile = (lid & 7) + ((lid >> 3) & 1) * 8;   // 0..15
    const int aKoff      = (lid >> 4) * 8;                     // 0 or 8
    const int bKInTile   = (lid & 7) + ((lid >> 3) & 1) * 8;   // 0..15
    const int bNoff      = (lid >> 4) * 8;                     // 0 or 8

    // cp.async per-thread mapping
    // A: 512 16B-chunks per tile (128 rows x 4); thread handles u = tid, tid+256
    // B: 512 16B-chunks (32 rows x 16)
    float acc[2][8][4];
    #pragma unroll
    for (int mt = 0; mt < 2; ++mt)
        #pragma unroll
        for (int nt = 0; nt < 8; ++nt)
            #pragma unroll
            for (int q = 0; q < 4; ++q) acc[mt][nt][q] = 0.0f;

    auto load_stage = [&](int kc, int s) {
        const uint32_t st = sbase + (uint32_t)s * STAGE_BYTES;
        const int kB = kc * BK;
        #pragma unroll
        for (int i = 0; i < 2; ++i) {
            const int u   = tid + i * 256;
            const int row = u >> 2;
            const int c4  = u & 3;
            const uint32_t so = (uint32_t)(row * A_STRIDE + c4 * 16);
            const size_t go = (size_t)(mBase + row) * Ktot + kB + c4 * 8;
            cp16(st + OFF_AH + so, g_Ah + go);
            cp16(st + OFF_AL + so, g_Al + go);
        }
        #pragma unroll
        for (int i = 0; i < 2; ++i) {
            const int u   = tid + i * 256;
            const int row = u >> 4;
            const int c16 = u & 15;
            cp16(st + OFF_B + (uint32_t)(row * B_STRIDE + c16 * 16),
                 g_B + (size_t)(kB + row) * FourH + nBase + c16 * 8);
        }
        CP_COMMIT();
    };

    load_stage(0, 0);
    load_stage(1, 1);

    #pragma unroll 1
    for (int kc = 0; kc < NKITERS; ++kc) {
        const int s = kc & 1;
        if (kc < NKITERS - 1) { CP_WAIT(1); } else { CP_WAIT(0); }
        __syncthreads();

        const uint32_t st = sbase + (uint32_t)s * STAGE_BYTES;

        #pragma unroll
        for (int kk = 0; kk < BK; kk += 16) {
            // load A fragments (hi + lo) for both m-tiles
            uint32_t af[2][4], al[2][4];
            #pragma unroll
            for (int mt = 0; mt < 2; ++mt) {
                const uint32_t ra = (uint32_t)((wm + mt * 16 + aRowInTile) * A_STRIDE
                                               + (kk + aKoff) * 2);
                LDSM_X4(af[mt][0], af[mt][1], af[mt][2], af[mt][3], st + OFF_AH + ra);
                LDSM_X4(al[mt][0], al[mt][1], al[mt][2], al[mt][3], st + OFF_AL + ra);
            }
            // load B fragments for 8 n-tiles (4 x4.trans loads)
            uint32_t bf[8][2];
            #pragma unroll
            for (int np = 0; np < 4; ++np) {
                const uint32_t rb = (uint32_t)((kk + bKInTile) * B_STRIDE
                                               + (wn + np * 16 + bNoff) * 2);
                uint32_t r0, r1, r2, r3;
                LDSM_X4_T(r0, r1, r2, r3, st + OFF_B + rb);
                bf[np * 2][0] = r0; bf[np * 2][1] = r1;
                bf[np * 2 + 1][0] = r2; bf[np * 2 + 1][1] = r3;
            }
            // MMAs: hi product + lo correction
            #pragma unroll
            for (int mt = 0; mt < 2; ++mt)
                #pragma unroll
                for (int nt = 0; nt < 8; ++nt) {
                    mma16816(acc[mt][nt], af[mt], bf[nt]);
                    mma16816(acc[mt][nt], al[mt], bf[nt]);
                }
        }
        __syncthreads();
        if (kc + 2 < NKITERS) load_stage(kc + 2, s);
    }

    // ---- epilogue: acc + bias -> g_a (fp32) ----
    const int tr = lid >> 2;           // 0..7
    const int tc = (lid & 3) * 2;      // 0,2,4,6
    #pragma unroll
    for (int mt = 0; mt < 2; ++mt) {
        #pragma unroll
        for (int nt = 0; nt < 8; ++nt) {
            const int r0 = mBase + wm + mt * 16 + tr;
            const int c  = nBase + wn + nt * 8 + tc;
            const float b0 = __ldg(bias + c);
            const float b1 = __ldg(bias + c + 1);
            float2 v0 = {acc[mt][nt][0] + b0, acc[mt][nt][1] + b1};
            float2 v1 = {acc[mt][nt][2] + b0, acc[mt][nt][3] + b1};
            *(float2*)(g_a + (size_t)r0 * FourH + c)       = v0;
            *(float2*)(g_a + (size_t)(r0 + 8) * FourH + c) = v1;
        }
    }
}

// ---------------------------------------------------------------------------
// LayerNorm + gates + cell update
// ---------------------------------------------------------------------------
__device__ __forceinline__ float sigmoidf_(float v) { return 1.0f / (1.0f + expf(-v)); }

__global__ __launch_bounds__(256)
void ln_gates_kernel(const float* __restrict__ prev_c,
                     const float* __restrict__ gamma,
                     const float* __restrict__ beta,
                     float* __restrict__ next_h,
                     float* __restrict__ next_c)
{
    const int row = blockIdx.x;
    const int tid = threadIdx.x;
    const int j   = tid * 4;
    const float* ar = g_a + (size_t)row * FourH;

    float4 v[4];
    #pragma unroll
    for (int s = 0; s < 4; ++s) v[s] = *(const float4*)(ar + s * Hh + j);

    float sum = 0.0f, sq = 0.0f;
    #pragma unroll
    for (int s = 0; s < 4; ++s) {
        sum += v[s].x + v[s].y + v[s].z + v[s].w;
        sq  += v[s].x * v[s].x + v[s].y * v[s].y + v[s].z * v[s].z + v[s].w * v[s].w;
    }
    #pragma unroll
    for (int off = 16; off > 0; off >>= 1) {
        sum += __shfl_xor_sync(0xffffffffu, sum, off);
        sq  += __shfl_xor_sync(0xffffffffu, sq,  off);
    }
    __shared__ float red_sum[8], red_sq[8];
    const int warp = tid >> 5;
    if ((tid & 31) == 0) { red_sum[warp] = sum; red_sq[warp] = sq; }
    __syncthreads();
    float tsum = 0.0f, tsq = 0.0f;
    #pragma unroll
    for (int w = 0; w < 8; ++w) { tsum += red_sum[w]; tsq += red_sq[w]; }

    const float inv_n = 1.0f / (float)FourH;
    const float mu   = tsum * inv_n;
    const float var  = tsq * inv_n - mu * mu;
    const float rstd = rsqrtf(var + 1e-5f);

    float n[4][4];
    #pragma unroll
    for (int s = 0; s < 4; ++s) {
        const float4 gm = *(const float4*)(gamma + s * Hh + j);
        const float4 bt = *(const float4*)(beta  + s * Hh + j);
        n[s][0] = (v[s].x - mu) * rstd * gm.x + bt.x;
        n[s][1] = (v[s].y - mu) * rstd * gm.y + bt.y;
        n[s][2] = (v[s].z - mu) * rstd * gm.z + bt.z;
        n[s][3] = (v[s].w - mu) * rstd * gm.w + bt.w;
    }

    const float4 pc = *(const float4*)(prev_c + (size_t)row * Hh + j);
    const float pcv[4] = {pc.x, pc.y, pc.z, pc.w};

    float4 hc, cc;
    float* hp = &hc.x;
    float* cp = &cc.x;
    #pragma unroll
    for (int c = 0; c < 4; ++c) {
        const float ig = sigmoidf_(n[0][c]);
        const float fg = sigmoidf_(n[1][c]);
        const float og = sigmoidf_(n[2][c]);
        const float gg = tanhf(n[3][c]);
        const float cn = fg * pcv[c] + ig * gg;
        cp[c] = cn;
        hp[c] = og * tanhf(cn);
    }
    *(float4*)(next_h + (size_t)row * Hh + j) = hc;
    *(float4*)(next_c + (size_t)row * Hh + j) = cc;
}

// ---------------------------------------------------------------------------
// Launch
// ---------------------------------------------------------------------------
extern "C" void kernel_launch(void* const* d_in, const int* in_sizes, int n_in,
                              void* d_out, int out_size)
{
    const float* x     = (const float*)d_in[0];
    const float* ph    = (const float*)d_in[1];
    const float* pc    = (const float*)d_in[2];
    const float* Wx    = (const float*)d_in[3];
    const float* Wh    = (const float*)d_in[4];
    const float* bias  = (const float*)d_in[5];
    const float* gamma = (const float*)d_in[6];
    const float* beta  = (const float*)d_in[7];

    float* out    = (float*)d_out;
    float* next_h = out;
    float* next_c = out + (size_t)out_size / 2;

    convertA_kernel<<<(Bsz * Ktot / 4) / 256, 256>>>(x, ph);
    convertB_kernel<<<(Ktot * FourH / 4) / 256, 256>>>(Wx, Wh);

    static bool attr_done = false;
    if (!attr_done) {
        cudaFuncSetAttribute(gemm_mma_kernel,
                             cudaFuncAttributeMaxDynamicSharedMemorySize, SMEM_TOTAL);
        attr_done = true;
    }
    gemm_mma_kernel<<<dim3(FourH / BN, Bsz / BM), GTHREADS, SMEM_TOTAL>>>(bias);

    ln_gates_kernel<<<Bsz, 256>>>(pc, gamma, beta, next_h, next_c);
}

// round 4
// speedup vs baseline: 6.0197x; 1.6757x over previous
#include <cuda_runtime.h>
#include <cuda_fp16.h>
#include <math.h>
#include <cstdint>

// ---------------------------------------------------------------------------
// Problem constants
// ---------------------------------------------------------------------------
#define Bsz   4096
#define Hh    1024
#define FourH 4096
#define Ktot  2048          // D + H concatenated

// GEMM tiling
#define BM 128
#define BN 128
#define BK 32
#define NKITERS (Ktot / BK)        // 64
#define GTHREADS 256
#define NSTAGES 3

// SMEM strides (bytes) — padded for conflict-free ldmatrix
#define A_STRIDE 80                 // 64B data + 16B pad
#define B_STRIDE 272                // 256B data + 16B pad
#define A_TILE_BYTES (BM * A_STRIDE)        // 10240
#define B_TILE_BYTES (BK * B_STRIDE)        // 8704
#define OFF_A  0
#define OFF_B  A_TILE_BYTES
#define STAGE_BYTES (A_TILE_BYTES + B_TILE_BYTES)   // 18944
#define SMEM_TOTAL (NSTAGES * STAGE_BYTES)          // 56832

// ---------------------------------------------------------------------------
// Device scratch
// ---------------------------------------------------------------------------
__device__ float  g_a[(size_t)Bsz * FourH];      // fp32 pre-activations (64 MB)
__device__ __half g_Ah[(size_t)Bsz * Ktot];      // A fp16 [4096][2048]
__device__ __half g_B [(size_t)Ktot * FourH];    // W fp16 [2048][4096]

// ---------------------------------------------------------------------------
// PTX helpers
// ---------------------------------------------------------------------------
__device__ __forceinline__ uint32_t smem_u32(const void* p) {
    uint32_t a;
    asm("{ .reg .u64 t; cvta.to.shared.u64 t, %1; cvt.u32.u64 %0, t; }" : "=r"(a) : "l"(p));
    return a;
}
__device__ __forceinline__ void cp16(uint32_t smem_addr, const void* gptr) {
    asm volatile("cp.async.cg.shared.global [%0], [%1], 16;" :: "r"(smem_addr), "l"(gptr));
}
#define CP_COMMIT() asm volatile("cp.async.commit_group;" ::: "memory")
#define CP_WAIT(n)  asm volatile("cp.async.wait_group %0;" :: "n"(n) : "memory")

#define LDSM_X4(r0,r1,r2,r3, addr) \
    asm volatile("ldmatrix.sync.aligned.m8n8.x4.shared.b16 {%0,%1,%2,%3}, [%4];" \
                 : "=r"(r0), "=r"(r1), "=r"(r2), "=r"(r3) : "r"(addr))
#define LDSM_X4_T(r0,r1,r2,r3, addr) \
    asm volatile("ldmatrix.sync.aligned.m8n8.x4.trans.shared.b16 {%0,%1,%2,%3}, [%4];" \
                 : "=r"(r0), "=r"(r1), "=r"(r2), "=r"(r3) : "r"(addr))

__device__ __forceinline__ void mma16816(float* c, const uint32_t* a, const uint32_t* b) {
    asm volatile(
        "mma.sync.aligned.m16n8k16.row.col.f32.f16.f16.f32 "
        "{%0,%1,%2,%3}, {%4,%5,%6,%7}, {%8,%9}, {%0,%1,%2,%3};"
        : "+f"(c[0]), "+f"(c[1]), "+f"(c[2]), "+f"(c[3])
        : "r"(a[0]), "r"(a[1]), "r"(a[2]), "r"(a[3]), "r"(b[0]), "r"(b[1]));
}

// ---------------------------------------------------------------------------
// convertA: [x | prev_h] -> fp16, row-major [4096][2048]
// ---------------------------------------------------------------------------
__global__ __launch_bounds__(256)
void convertA_kernel(const float* __restrict__ x, const float* __restrict__ ph) {
    const int idx = blockIdx.x * 256 + threadIdx.x;     // 2M float4 groups
    const int row = idx >> 9;
    const int col = (idx & 511) * 4;
    const float* src = (col < 1024) ? (x + (size_t)row * 1024 + col)
                                    : (ph + (size_t)row * 1024 + (col - 1024));
    const float4 v = *(const float4*)src;
    const size_t off = (size_t)row * Ktot + col;
    *(__half2*)(g_Ah + off)     = __halves2half2(__float2half_rn(v.x), __float2half_rn(v.y));
    *(__half2*)(g_Ah + off + 2) = __halves2half2(__float2half_rn(v.z), __float2half_rn(v.w));
}

// ---------------------------------------------------------------------------
// convertB: W = [Wx ; Wh] (natural [k][n] layout) -> fp16
// ---------------------------------------------------------------------------
__global__ __launch_bounds__(256)
void convertB_kernel(const float* __restrict__ Wx, const float* __restrict__ Wh) {
    const int idx = blockIdx.x * 256 + threadIdx.x;     // 2M float4 groups
    const int row = idx >> 10;
    const int col = (idx & 1023) * 4;
    const float* src = (row < 1024) ? (Wx + (size_t)row * FourH + col)
                                    : (Wh + (size_t)(row - 1024) * FourH + col);
    const float4 v = *(const float4*)src;
    const size_t off = (size_t)row * FourH + col;
    *(__half2*)(g_B + off)     = __halves2half2(__float2half_rn(v.x), __float2half_rn(v.y));
    *(__half2*)(g_B + off + 2) = __halves2half2(__float2half_rn(v.z), __float2half_rn(v.w));
}

// ---------------------------------------------------------------------------
// Tensor-core GEMM: g_a = A @ B + bias  (single-pass fp16)
// CTA 128x128, BK=32, 8 warps (4 m x 2 n), warp tile 32x64, 3-stage pipeline.
// ---------------------------------------------------------------------------
__global__ __launch_bounds__(GTHREADS, 2)
void gemm_mma_kernel(const float* __restrict__ bias) {
    extern __shared__ char smem[];
    const uint32_t sbase = smem_u32(smem);
    const int tid  = threadIdx.x;
    const int warp = tid >> 5;
    const int lid  = tid & 31;

    const int mBase = blockIdx.y * BM;
    const int nBase = blockIdx.x * BN;

    const int warpM = warp & 3;
    const int warpN = warp >> 2;
    const int wm = warpM * 32;
    const int wn = warpN * 64;

    // ldmatrix per-thread row mapping
    const int aRowInTile = (lid & 7) + ((lid >> 3) & 1) * 8;   // 0..15
    const int aKoff      = (lid >> 4) * 8;                     // 0 or 8
    const int bKInTile   = (lid & 7) + ((lid >> 3) & 1) * 8;   // 0..15
    const int bNoff      = (lid >> 4) * 8;                     // 0 or 8

    float acc[2][8][4];
    #pragma unroll
    for (int mt = 0; mt < 2; ++mt)
        #pragma unroll
        for (int nt = 0; nt < 8; ++nt)
            #pragma unroll
            for (int q = 0; q < 4; ++q) acc[mt][nt][q] = 0.0f;

    auto load_stage = [&](int kc, int s) {
        const uint32_t st = sbase + (uint32_t)s * STAGE_BYTES;
        const int kB = kc * BK;
        // A: 128 rows x 64B = 512 16B-chunks
        #pragma unroll
        for (int i = 0; i < 2; ++i) {
            const int u   = tid + i * 256;
            const int row = u >> 2;
            const int c4  = u & 3;
            cp16(st + OFF_A + (uint32_t)(row * A_STRIDE + c4 * 16),
                 g_Ah + (size_t)(mBase + row) * Ktot + kB + c4 * 8);
        }
        // B: 32 rows x 256B = 512 16B-chunks
        #pragma unroll
        for (int i = 0; i < 2; ++i) {
            const int u   = tid + i * 256;
            const int row = u >> 4;
            const int c16 = u & 15;
            cp16(st + OFF_B + (uint32_t)(row * B_STRIDE + c16 * 16),
                 g_B + (size_t)(kB + row) * FourH + nBase + c16 * 8);
        }
        CP_COMMIT();
    };

    load_stage(0, 0);
    load_stage(1, 1);
    load_stage(2, 2);

    int s = 0;
    #pragma unroll 1
    for (int kc = 0; kc < NKITERS; ++kc) {
        if (kc < NKITERS - 2) { CP_WAIT(2); }
        else if (kc == NKITERS - 2) { CP_WAIT(1); }
        else { CP_WAIT(0); }
        __syncthreads();

        const uint32_t st = sbase + (uint32_t)s * STAGE_BYTES;

        #pragma unroll
        for (int kk = 0; kk < BK; kk += 16) {
            uint32_t af[2][4];
            #pragma unroll
            for (int mt = 0; mt < 2; ++mt) {
                const uint32_t ra = (uint32_t)((wm + mt * 16 + aRowInTile) * A_STRIDE
                                               + (kk + aKoff) * 2);
                LDSM_X4(af[mt][0], af[mt][1], af[mt][2], af[mt][3], st + OFF_A + ra);
            }
            uint32_t bf[8][2];
            #pragma unroll
            for (int np = 0; np < 4; ++np) {
                const uint32_t rb = (uint32_t)((kk + bKInTile) * B_STRIDE
                                               + (wn + np * 16 + bNoff) * 2);
                uint32_t r0, r1, r2, r3;
                LDSM_X4_T(r0, r1, r2, r3, st + OFF_B + rb);
                bf[np * 2][0] = r0;     bf[np * 2][1] = r1;
                bf[np * 2 + 1][0] = r2; bf[np * 2 + 1][1] = r3;
            }
            #pragma unroll
            for (int mt = 0; mt < 2; ++mt)
                #pragma unroll
                for (int nt = 0; nt < 8; ++nt)
                    mma16816(acc[mt][nt], af[mt], bf[nt]);
        }
        __syncthreads();
        if (kc + NSTAGES < NKITERS) load_stage(kc + NSTAGES, s);
        s = (s == NSTAGES - 1) ? 0 : s + 1;
    }

    // ---- epilogue: acc + bias -> g_a ----
    const int tr = lid >> 2;
    const int tc = (lid & 3) * 2;
    #pragma unroll
    for (int mt = 0; mt < 2; ++mt) {
        #pragma unroll
        for (int nt = 0; nt < 8; ++nt) {
            const int r0 = mBase + wm + mt * 16 + tr;
            const int c  = nBase + wn + nt * 8 + tc;
            const float b0 = __ldg(bias + c);
            const float b1 = __ldg(bias + c + 1);
            float2 v0 = {acc[mt][nt][0] + b0, acc[mt][nt][1] + b1};
            float2 v1 = {acc[mt][nt][2] + b0, acc[mt][nt][3] + b1};
            *(float2*)(g_a + (size_t)r0 * FourH + c)       = v0;
            *(float2*)(g_a + (size_t)(r0 + 8) * FourH + c) = v1;
        }
    }
}

// ---------------------------------------------------------------------------
// LayerNorm + gates + cell update
// ---------------------------------------------------------------------------
__device__ __forceinline__ float sigmoidf_(float v) { return 1.0f / (1.0f + expf(-v)); }

__global__ __launch_bounds__(256)
void ln_gates_kernel(const float* __restrict__ prev_c,
                     const float* __restrict__ gamma,
                     const float* __restrict__ beta,
                     float* __restrict__ next_h,
                     float* __restrict__ next_c)
{
    const int row = blockIdx.x;
    const int tid = threadIdx.x;
    const int j   = tid * 4;
    const float* ar = g_a + (size_t)row * FourH;

    float4 v[4];
    #pragma unroll
    for (int s = 0; s < 4; ++s) v[s] = *(const float4*)(ar + s * Hh + j);

    float sum = 0.0f, sq = 0.0f;
    #pragma unroll
    for (int s = 0; s < 4; ++s) {
        sum += v[s].x + v[s].y + v[s].z + v[s].w;
        sq  += v[s].x * v[s].x + v[s].y * v[s].y + v[s].z * v[s].z + v[s].w * v[s].w;
    }
    #pragma unroll
    for (int off = 16; off > 0; off >>= 1) {
        sum += __shfl_xor_sync(0xffffffffu, sum, off);
        sq  += __shfl_xor_sync(0xffffffffu, sq,  off);
    }
    __shared__ float red_sum[8], red_sq[8];
    const int warp = tid >> 5;
    if ((tid & 31) == 0) { red_sum[warp] = sum; red_sq[warp] = sq; }
    __syncthreads();
    float tsum = 0.0f, tsq = 0.0f;
    #pragma unroll
    for (int w = 0; w < 8; ++w) { tsum += red_sum[w]; tsq += red_sq[w]; }

    const float inv_n = 1.0f / (float)FourH;
    const float mu   = tsum * inv_n;
    const float var  = tsq * inv_n - mu * mu;
    const float rstd = rsqrtf(var + 1e-5f);

    float n[4][4];
    #pragma unroll
    for (int s = 0; s < 4; ++s) {
        const float4 gm = *(const float4*)(gamma + s * Hh + j);
        const float4 bt = *(const float4*)(beta  + s * Hh + j);
        n[s][0] = (v[s].x - mu) * rstd * gm.x + bt.x;
        n[s][1] = (v[s].y - mu) * rstd * gm.y + bt.y;
        n[s][2] = (v[s].z - mu) * rstd * gm.z + bt.z;
        n[s][3] = (v[s].w - mu) * rstd * gm.w + bt.w;
    }

    const float4 pc = *(const float4*)(prev_c + (size_t)row * Hh + j);
    const float pcv[4] = {pc.x, pc.y, pc.z, pc.w};

    float4 hc, cc;
    float* hp = &hc.x;
    float* cp = &cc.x;
    #pragma unroll
    for (int c = 0; c < 4; ++c) {
        const float ig = sigmoidf_(n[0][c]);
        const float fg = sigmoidf_(n[1][c]);
        const float og = sigmoidf_(n[2][c]);
        const float gg = tanhf(n[3][c]);
        const float cn = fg * pcv[c] + ig * gg;
        cp[c] = cn;
        hp[c] = og * tanhf(cn);
    }
    *(float4*)(next_h + (size_t)row * Hh + j) = hc;
    *(float4*)(next_c + (size_t)row * Hh + j) = cc;
}

// ---------------------------------------------------------------------------
// Launch
// ---------------------------------------------------------------------------
extern "C" void kernel_launch(void* const* d_in, const int* in_sizes, int n_in,
                              void* d_out, int out_size)
{
    const float* x     = (const float*)d_in[0];
    const float* ph    = (const float*)d_in[1];
    const float* pc    = (const float*)d_in[2];
    const float* Wx    = (const float*)d_in[3];
    const float* Wh    = (const float*)d_in[4];
    const float* bias  = (const float*)d_in[5];
    const float* gamma = (const float*)d_in[6];
    const float* beta  = (const float*)d_in[7];

    float* out    = (float*)d_out;
    float* next_h = out;
    float* next_c = out + (size_t)out_size / 2;

    convertA_kernel<<<(Bsz * Ktot / 4) / 256, 256>>>(x, ph);
    convertB_kernel<<<(Ktot * FourH / 4) / 256, 256>>>(Wx, Wh);

    static bool attr_done = false;
    if (!attr_done) {
        cudaFuncSetAttribute(gemm_mma_kernel,
                             cudaFuncAttributeMaxDynamicSharedMemorySize, SMEM_TOTAL);
        attr_done = true;
    }
    gemm_mma_kernel<<<dim3(FourH / BN, Bsz / BM), GTHREADS, SMEM_TOTAL>>>(bias);

    ln_gates_kernel<<<Bsz, 256>>>(pc, gamma, beta, next_h, next_c);
}